// round 9
// baseline (speedup 1.0000x reference)
#include <cuda_runtime.h>
#include <cuda_fp16.h>

// GCN_56882546868697 — R9 = R5 (best 129.1us) + vectorized GEMM2 in agg1l2:
// float4 sact rows + transposed padded W1 in smem -> 4x fewer LDS instructions,
// ~2x fewer LDS wavefronts in the measured-hot phase.

#define NN 100000
#define NE 1600000
#define DF 64
#define LT 64
#define NC 16
#define NEG 0.01f
#define PAD 68    // row stride (floats): 16B-aligned, 4-bank skew per row/col

// ---- static scratch ----
__device__ __align__(16) __half g_h[NN * LT];
__device__ __align__(16) __half g_z[NN * NC];
__device__ int g_degs[NN];
__device__ int g_degr[NN];
__device__ int g_beg[NN];
__device__ int g_cur[NN];
__device__ int g_csr[NE];
__device__ int g_total;

// ---------------------------------------------------------------- init (split per branch)
__global__ void k_init_r(int nn) {
    const int stride = gridDim.x * blockDim.x;
    int t0 = blockIdx.x * blockDim.x + threadIdx.x;
    for (int i = t0; i < nn; i += stride) g_degr[i] = 0;
    if (t0 == 0) g_total = 0;
}
__global__ void k_init_s(int nn) {
    const int stride = gridDim.x * blockDim.x;
    for (int i = blockIdx.x * blockDim.x + threadIdx.x; i < nn; i += stride) g_degs[i] = 0;
}

// ---------------------------------------------------------------- degree histograms
__global__ void k_hist_s(const int* __restrict__ senders, int ne) {
    int t = blockIdx.x * blockDim.x + threadIdx.x;
    int e0 = t * 4;
    if (e0 + 3 < ne) {
        int4 s = *reinterpret_cast<const int4*>(&senders[e0]);
        atomicAdd(&g_degs[s.x], 1); atomicAdd(&g_degs[s.y], 1);
        atomicAdd(&g_degs[s.z], 1); atomicAdd(&g_degs[s.w], 1);
    } else {
        for (int e = e0; e < ne; ++e) atomicAdd(&g_degs[__ldg(&senders[e])], 1);
    }
}
__global__ void k_hist_r(const int* __restrict__ receivers, int ne) {
    int t = blockIdx.x * blockDim.x + threadIdx.x;
    int e0 = t * 4;
    if (e0 + 3 < ne) {
        int4 r = *reinterpret_cast<const int4*>(&receivers[e0]);
        atomicAdd(&g_degr[r.x], 1); atomicAdd(&g_degr[r.y], 1);
        atomicAdd(&g_degr[r.z], 1); atomicAdd(&g_degr[r.w], 1);
    } else {
        for (int e = e0; e < ne; ++e) atomicAdd(&g_degr[__ldg(&receivers[e])], 1);
    }
}

// ---------------------------------------------------------------- segment offsets (warp scan)
__global__ void k_offsets(int nn) {
    int i = blockIdx.x * blockDim.x + threadIdx.x;
    int lane = threadIdx.x & 31;
    int d = (i < nn) ? g_degr[i] : 0;
    int pre = d;
#pragma unroll
    for (int o = 1; o < 32; o <<= 1) {
        int v = __shfl_up_sync(0xffffffffu, pre, o);
        if (lane >= o) pre += v;
    }
    int excl = pre - d;
    int wsum = __shfl_sync(0xffffffffu, pre, 31);
    int base = 0;
    if (lane == 0) base = atomicAdd(&g_total, wsum);
    base = __shfl_sync(0xffffffffu, base, 0);
    if (i < nn) {
        int b = base + excl;
        g_beg[i] = b;
        g_cur[i] = b;
    }
}

// ---------------------------------------------------------------- bin (2 concurrent streams)
__global__ void k_bin(const int* __restrict__ senders,
                      const int* __restrict__ receivers, int ne) {
    int t = blockIdx.x * blockDim.x + threadIdx.x;
    int e0 = t * 4;
    if (e0 + 3 < ne) {
        int4 s = *reinterpret_cast<const int4*>(&senders[e0]);
        int4 r = *reinterpret_cast<const int4*>(&receivers[e0]);
        int p0 = atomicAdd(&g_cur[r.x], 1);
        int p1 = atomicAdd(&g_cur[r.y], 1);
        int p2 = atomicAdd(&g_cur[r.z], 1);
        int p3 = atomicAdd(&g_cur[r.w], 1);
        g_csr[p0] = s.x; g_csr[p1] = s.y; g_csr[p2] = s.z; g_csr[p3] = s.w;
    } else {
        for (int e = e0; e < ne; ++e) {
            int r = __ldg(&receivers[e]);
            g_csr[atomicAdd(&g_cur[r], 1)] = __ldg(&senders[e]);
        }
    }
}

// ---------------------------------------------------------------- GEMM1 + sender norm -> fp16
__global__ void k_gemm1(const float* __restrict__ nodes,
                        const float* __restrict__ W0,
                        const float* __restrict__ b0, int nn) {
    __shared__ __align__(16) float sW[DF * LT];
    __shared__ float sx[64][DF + 1];
    const int tid = threadIdx.x;
    const int row0 = blockIdx.x * 64;

    for (int i = tid; i < DF * LT; i += 256) sW[i] = W0[i];
    for (int idx = tid; idx < 64 * 16; idx += 256) {
        int r = idx >> 4, k0 = (idx & 15) * 4;
        int grow = row0 + r;
        float4 v = (grow < nn)
            ? *reinterpret_cast<const float4*>(&nodes[grow * DF + k0])
            : make_float4(0.f, 0.f, 0.f, 0.f);
        sx[r][k0] = v.x; sx[r][k0 + 1] = v.y; sx[r][k0 + 2] = v.z; sx[r][k0 + 3] = v.w;
    }
    __syncthreads();

    const int ty = tid >> 4, tx = tid & 15;
    const int r0 = ty * 4, c0 = tx * 4;

    unsigned long long acc[4][2];
#pragma unroll
    for (int i = 0; i < 4; ++i) { acc[i][0] = 0ull; acc[i][1] = 0ull; }

#pragma unroll
    for (int k = 0; k < DF; ++k) {
        ulonglong2 b2 = *reinterpret_cast<const ulonglong2*>(&sW[k * LT + c0]);
#pragma unroll
        for (int i = 0; i < 4; ++i) {
            float a = sx[r0 + i][k];
            unsigned long long ap;
            asm("mov.b64 %0, {%1, %1};" : "=l"(ap) : "r"(__float_as_uint(a)));
            asm("fma.rn.f32x2 %0, %1, %2, %0;" : "+l"(acc[i][0]) : "l"(ap), "l"(b2.x));
            asm("fma.rn.f32x2 %0, %1, %2, %0;" : "+l"(acc[i][1]) : "l"(ap), "l"(b2.y));
        }
    }

    const float4 bias = *reinterpret_cast<const float4*>(&b0[c0]);
#pragma unroll
    for (int i = 0; i < 4; ++i) {
        int grow = row0 + r0 + i;
        if (grow < nn) {
            unsigned lo0, hi0, lo1, hi1;
            asm("mov.b64 {%0, %1}, %2;" : "=r"(lo0), "=r"(hi0) : "l"(acc[i][0]));
            asm("mov.b64 {%0, %1}, %2;" : "=r"(lo1), "=r"(hi1) : "l"(acc[i][1]));
            float s = rsqrtf(fmaxf((float)g_degs[grow], 1.0f));
            float ox = (__uint_as_float(lo0) + bias.x) * s;
            float oy = (__uint_as_float(hi0) + bias.y) * s;
            float oz = (__uint_as_float(lo1) + bias.z) * s;
            float ow = (__uint_as_float(hi1) + bias.w) * s;
            __half2 h0 = __floats2half2_rn(ox, oy);
            __half2 h1 = __floats2half2_rn(oz, ow);
            uint2 st;
            st.x = *reinterpret_cast<unsigned*>(&h0);
            st.y = *reinterpret_cast<unsigned*>(&h1);
            *reinterpret_cast<uint2*>(&g_h[grow * LT + c0]) = st;
        }
    }
}

// ---------------------------------------------------------------- agg1 + norm + leaky + GEMM2 + sigmoid
// Gather phase unchanged from R5; GEMM2 phase vectorized:
//   sact rows float4-aligned (stride PAD), W1 transposed [c][k] (stride PAD)
//   -> inner loop is 16 x (2x LDS.128 + 4 FFMA) instead of 64 x (2x LDS.32 + FFMA)
__global__ void k_agg1l2(const float* __restrict__ W1,
                         const float* __restrict__ b1, int nn) {
    __shared__ __align__(16) float sW1t[NC * PAD];   // [c][k], transposed, padded
    __shared__ __align__(16) float sact[16][PAD];    // [node][k], padded
    const int tid = threadIdx.x;
    // transpose W1 (64x16 -> [c][k]) once per block
    for (int i = tid; i < LT * NC; i += 256) {
        int c = i >> 6, k = i & 63;
        sW1t[c * PAD + k] = W1[k * NC + c];
    }

    const int ln = tid >> 4;
    const int c  = tid & 15;
    const int node = blockIdx.x * 16 + ln;

    if (node < nn) {
        int beg = g_beg[node];
        int deg = g_degr[node];
        int end = beg + deg;
        float ax = 0.f, ay = 0.f, az = 0.f, aw = 0.f;
        int i = beg;
        for (; i + 4 <= end; i += 4) {
            int s0 = __ldg(&g_csr[i]);
            int s1 = __ldg(&g_csr[i + 1]);
            int s2 = __ldg(&g_csr[i + 2]);
            int s3 = __ldg(&g_csr[i + 3]);
            uint2 u0 = *reinterpret_cast<const uint2*>(&g_h[s0 * LT + c * 4]);
            uint2 u1 = *reinterpret_cast<const uint2*>(&g_h[s1 * LT + c * 4]);
            uint2 u2 = *reinterpret_cast<const uint2*>(&g_h[s2 * LT + c * 4]);
            uint2 u3 = *reinterpret_cast<const uint2*>(&g_h[s3 * LT + c * 4]);
            float2 a0 = __half22float2(*reinterpret_cast<__half2*>(&u0.x));
            float2 b0_ = __half22float2(*reinterpret_cast<__half2*>(&u0.y));
            float2 a1 = __half22float2(*reinterpret_cast<__half2*>(&u1.x));
            float2 b1_ = __half22float2(*reinterpret_cast<__half2*>(&u1.y));
            float2 a2 = __half22float2(*reinterpret_cast<__half2*>(&u2.x));
            float2 b2_ = __half22float2(*reinterpret_cast<__half2*>(&u2.y));
            float2 a3 = __half22float2(*reinterpret_cast<__half2*>(&u3.x));
            float2 b3_ = __half22float2(*reinterpret_cast<__half2*>(&u3.y));
            ax += a0.x + a1.x + a2.x + a3.x;
            ay += a0.y + a1.y + a2.y + a3.y;
            az += b0_.x + b1_.x + b2_.x + b3_.x;
            aw += b0_.y + b1_.y + b2_.y + b3_.y;
        }
        for (; i < end; ++i) {
            int s = __ldg(&g_csr[i]);
            uint2 u = *reinterpret_cast<const uint2*>(&g_h[s * LT + c * 4]);
            float2 f0 = __half22float2(*reinterpret_cast<__half2*>(&u.x));
            float2 f1 = __half22float2(*reinterpret_cast<__half2*>(&u.y));
            ax += f0.x; ay += f0.y; az += f1.x; aw += f1.y;
        }
        float dr = rsqrtf(fmaxf((float)deg, 1.0f));
        ax *= dr; ay *= dr; az *= dr; aw *= dr;
        ax = (ax >= 0.f) ? ax : NEG * ax;
        ay = (ay >= 0.f) ? ay : NEG * ay;
        az = (az >= 0.f) ? az : NEG * az;
        aw = (aw >= 0.f) ? aw : NEG * aw;
        float4 st; st.x = ax; st.y = ay; st.z = az; st.w = aw;
        *reinterpret_cast<float4*>(&sact[ln][c * 4]) = st;   // 16B-aligned (PAD=68)
    }
    __syncthreads();

    if (node >= nn) return;
    float acc = __ldg(&b1[c]);
    const float* wcol = &sW1t[c * PAD];
#pragma unroll
    for (int kg = 0; kg < 16; ++kg) {
        float4 a = *reinterpret_cast<const float4*>(&sact[ln][kg * 4]);   // broadcast
        float4 w = *reinterpret_cast<const float4*>(&wcol[kg * 4]);
        acc += a.x * w.x + a.y * w.y + a.z * w.z + a.w * w.w;
    }
    float zz = 1.0f / (1.0f + __expf(-acc));
    g_z[node * NC + c] = __float2half_rn(zz);
}

// ---------------------------------------------------------------- agg2 (R5: 2 thr/node)
__global__ void k_agg2(float* __restrict__ out, int nn) {
    const int t = blockIdx.x * blockDim.x + threadIdx.x;
    const int node = t >> 1;
    const int c = t & 1;
    if (node >= nn) return;
    int beg = g_beg[node];
    int end = beg + g_degr[node];
    float a[8] = {};
    int i = beg;
    for (; i + 2 <= end; i += 2) {
        int s0 = __ldg(&g_csr[i]);
        int s1 = __ldg(&g_csr[i + 1]);
        uint4 u0 = *reinterpret_cast<const uint4*>(&g_z[s0 * NC + c * 8]);
        uint4 u1 = *reinterpret_cast<const uint4*>(&g_z[s1 * NC + c * 8]);
        float2 f;
        f = __half22float2(*reinterpret_cast<__half2*>(&u0.x)); a[0] += f.x; a[1] += f.y;
        f = __half22float2(*reinterpret_cast<__half2*>(&u0.y)); a[2] += f.x; a[3] += f.y;
        f = __half22float2(*reinterpret_cast<__half2*>(&u0.z)); a[4] += f.x; a[5] += f.y;
        f = __half22float2(*reinterpret_cast<__half2*>(&u0.w)); a[6] += f.x; a[7] += f.y;
        f = __half22float2(*reinterpret_cast<__half2*>(&u1.x)); a[0] += f.x; a[1] += f.y;
        f = __half22float2(*reinterpret_cast<__half2*>(&u1.y)); a[2] += f.x; a[3] += f.y;
        f = __half22float2(*reinterpret_cast<__half2*>(&u1.z)); a[4] += f.x; a[5] += f.y;
        f = __half22float2(*reinterpret_cast<__half2*>(&u1.w)); a[6] += f.x; a[7] += f.y;
    }
    for (; i < end; ++i) {
        int s = __ldg(&g_csr[i]);
        uint4 u = *reinterpret_cast<const uint4*>(&g_z[s * NC + c * 8]);
        float2 f;
        f = __half22float2(*reinterpret_cast<__half2*>(&u.x)); a[0] += f.x; a[1] += f.y;
        f = __half22float2(*reinterpret_cast<__half2*>(&u.y)); a[2] += f.x; a[3] += f.y;
        f = __half22float2(*reinterpret_cast<__half2*>(&u.z)); a[4] += f.x; a[5] += f.y;
        f = __half22float2(*reinterpret_cast<__half2*>(&u.w)); a[6] += f.x; a[7] += f.y;
    }
    float4 o0 = make_float4(a[0], a[1], a[2], a[3]);
    float4 o1 = make_float4(a[4], a[5], a[6], a[7]);
    *reinterpret_cast<float4*>(&out[node * NC + c * 8])     = o0;
    *reinterpret_cast<float4*>(&out[node * NC + c * 8 + 4]) = o1;
}

// ---------------------------------------------------------------- launch (R5 fork/join, split bin)
extern "C" void kernel_launch(void* const* d_in, const int* in_sizes, int n_in,
                              void* d_out, int out_size) {
    const float* nodes     = (const float*)d_in[0];
    const int*   senders   = (const int*)  d_in[1];
    const int*   receivers = (const int*)  d_in[2];
    const float* W0        = (const float*)d_in[3];
    const float* b0        = (const float*)d_in[4];
    const float* W1        = (const float*)d_in[5];
    const float* b1        = (const float*)d_in[6];
    float*       out       = (float*)d_out;

    const int nn = in_sizes[0] / DF;
    const int ne = in_sizes[1];
    const int eg = ((ne + 3) / 4 + 255) / 256;

    static cudaStream_t s2 = 0;
    static cudaEvent_t evFork = 0, evJoin = 0;
    if (!s2) {
        cudaStreamCreateWithFlags(&s2, cudaStreamNonBlocking);
        cudaEventCreateWithFlags(&evFork, cudaEventDisableTiming);
        cudaEventCreateWithFlags(&evJoin, cudaEventDisableTiming);
    }

    // fork at t=0
    cudaEventRecord(evFork, 0);
    cudaStreamWaitEvent(s2, evFork, 0);

    // branch B (s2): init degs -> hist_s -> GEMM1
    k_init_s<<<128, 256, 0, s2>>>(nn);
    k_hist_s<<<eg, 256, 0, s2>>>(senders, ne);
    k_gemm1<<<(nn + 63) / 64, 256, 0, s2>>>(nodes, W0, b0, nn);
    cudaEventRecord(evJoin, s2);

    // branch A (s0): init degr -> hist_r -> offsets -> bin
    k_init_r<<<128, 256>>>(nn);
    k_hist_r<<<eg, 256>>>(receivers, ne);
    k_offsets<<<(nn + 255) / 256, 256>>>(nn);
    k_bin<<<eg, 256>>>(senders, receivers, ne);

    // join
    cudaStreamWaitEvent(0, evJoin, 0);
    k_agg1l2<<<(nn + 15) / 16, 256>>>(W1, b1, nn);
    k_agg2<<<(nn * 2 + 255) / 256, 256>>>(out, nn);
}

// round 10
// speedup vs baseline: 1.0678x; 1.0678x over previous
#include <cuda_runtime.h>
#include <cuda_fp16.h>

// GCN_56882546868697 — R10 = R5 (best 129.1us, pipeline/launch verbatim) with
// ONLY k_agg1l2 rewritten: 8-lane-per-node gather (coalesced index batches,
// upfront shfl distribution, 8 independent LDG.128 in flight) + vectorized GEMM2.

#define NN 100000
#define NE 1600000
#define DF 64
#define LT 64
#define NC 16
#define NEG 0.01f
#define PAD 68

// ---- static scratch ----
__device__ __align__(16) __half g_h[NN * LT];
__device__ __align__(16) __half g_z[NN * NC];
__device__ int g_degs[NN];
__device__ int g_degr[NN];
__device__ int g_beg[NN];
__device__ int g_cur[NN];
__device__ int g_csr[NE];
__device__ int g_total;

// ---------------------------------------------------------------- init (R5)
__global__ void k_init(int nn) {
    const int stride = gridDim.x * blockDim.x;
    int t0 = blockIdx.x * blockDim.x + threadIdx.x;
    for (int i = t0; i < nn; i += stride) { g_degs[i] = 0; g_degr[i] = 0; }
    if (t0 == 0) g_total = 0;
}

// ---------------------------------------------------------------- degree histograms (R5)
__global__ void k_hist_s(const int* __restrict__ senders, int ne) {
    int t = blockIdx.x * blockDim.x + threadIdx.x;
    int e0 = t * 4;
    if (e0 + 3 < ne) {
        int4 s = *reinterpret_cast<const int4*>(&senders[e0]);
        atomicAdd(&g_degs[s.x], 1); atomicAdd(&g_degs[s.y], 1);
        atomicAdd(&g_degs[s.z], 1); atomicAdd(&g_degs[s.w], 1);
    } else {
        for (int e = e0; e < ne; ++e) atomicAdd(&g_degs[__ldg(&senders[e])], 1);
    }
}
__global__ void k_hist_r(const int* __restrict__ receivers, int ne) {
    int t = blockIdx.x * blockDim.x + threadIdx.x;
    int e0 = t * 4;
    if (e0 + 3 < ne) {
        int4 r = *reinterpret_cast<const int4*>(&receivers[e0]);
        atomicAdd(&g_degr[r.x], 1); atomicAdd(&g_degr[r.y], 1);
        atomicAdd(&g_degr[r.z], 1); atomicAdd(&g_degr[r.w], 1);
    } else {
        for (int e = e0; e < ne; ++e) atomicAdd(&g_degr[__ldg(&receivers[e])], 1);
    }
}

// ---------------------------------------------------------------- offsets (R5 warp scan)
__global__ void k_offsets(int nn) {
    int i = blockIdx.x * blockDim.x + threadIdx.x;
    int lane = threadIdx.x & 31;
    int d = (i < nn) ? g_degr[i] : 0;
    int pre = d;
#pragma unroll
    for (int o = 1; o < 32; o <<= 1) {
        int v = __shfl_up_sync(0xffffffffu, pre, o);
        if (lane >= o) pre += v;
    }
    int excl = pre - d;
    int wsum = __shfl_sync(0xffffffffu, pre, 31);
    int base = 0;
    if (lane == 0) base = atomicAdd(&g_total, wsum);
    base = __shfl_sync(0xffffffffu, base, 0);
    if (i < nn) {
        int b = base + excl;
        g_beg[i] = b;
        g_cur[i] = b;
    }
}

// ---------------------------------------------------------------- bin (R5)
__global__ void k_bin(const int* __restrict__ senders,
                      const int* __restrict__ receivers, int ne) {
    int t = blockIdx.x * blockDim.x + threadIdx.x;
    int e0 = t * 4;
    if (e0 + 3 < ne) {
        int4 s = *reinterpret_cast<const int4*>(&senders[e0]);
        int4 r = *reinterpret_cast<const int4*>(&receivers[e0]);
        int p0 = atomicAdd(&g_cur[r.x], 1);
        int p1 = atomicAdd(&g_cur[r.y], 1);
        int p2 = atomicAdd(&g_cur[r.z], 1);
        int p3 = atomicAdd(&g_cur[r.w], 1);
        g_csr[p0] = s.x; g_csr[p1] = s.y; g_csr[p2] = s.z; g_csr[p3] = s.w;
    } else {
        for (int e = e0; e < ne; ++e) {
            int r = __ldg(&receivers[e]);
            g_csr[atomicAdd(&g_cur[r], 1)] = __ldg(&senders[e]);
        }
    }
}

// ---------------------------------------------------------------- GEMM1 (R5)
__global__ void k_gemm1(const float* __restrict__ nodes,
                        const float* __restrict__ W0,
                        const float* __restrict__ b0, int nn) {
    __shared__ __align__(16) float sW[DF * LT];
    __shared__ float sx[64][DF + 1];
    const int tid = threadIdx.x;
    const int row0 = blockIdx.x * 64;

    for (int i = tid; i < DF * LT; i += 256) sW[i] = W0[i];
    for (int idx = tid; idx < 64 * 16; idx += 256) {
        int r = idx >> 4, k0 = (idx & 15) * 4;
        int grow = row0 + r;
        float4 v = (grow < nn)
            ? *reinterpret_cast<const float4*>(&nodes[grow * DF + k0])
            : make_float4(0.f, 0.f, 0.f, 0.f);
        sx[r][k0] = v.x; sx[r][k0 + 1] = v.y; sx[r][k0 + 2] = v.z; sx[r][k0 + 3] = v.w;
    }
    __syncthreads();

    const int ty = tid >> 4, tx = tid & 15;
    const int r0 = ty * 4, c0 = tx * 4;

    unsigned long long acc[4][2];
#pragma unroll
    for (int i = 0; i < 4; ++i) { acc[i][0] = 0ull; acc[i][1] = 0ull; }

#pragma unroll
    for (int k = 0; k < DF; ++k) {
        ulonglong2 b2 = *reinterpret_cast<const ulonglong2*>(&sW[k * LT + c0]);
#pragma unroll
        for (int i = 0; i < 4; ++i) {
            float a = sx[r0 + i][k];
            unsigned long long ap;
            asm("mov.b64 %0, {%1, %1};" : "=l"(ap) : "r"(__float_as_uint(a)));
            asm("fma.rn.f32x2 %0, %1, %2, %0;" : "+l"(acc[i][0]) : "l"(ap), "l"(b2.x));
            asm("fma.rn.f32x2 %0, %1, %2, %0;" : "+l"(acc[i][1]) : "l"(ap), "l"(b2.y));
        }
    }

    const float4 bias = *reinterpret_cast<const float4*>(&b0[c0]);
#pragma unroll
    for (int i = 0; i < 4; ++i) {
        int grow = row0 + r0 + i;
        if (grow < nn) {
            unsigned lo0, hi0, lo1, hi1;
            asm("mov.b64 {%0, %1}, %2;" : "=r"(lo0), "=r"(hi0) : "l"(acc[i][0]));
            asm("mov.b64 {%0, %1}, %2;" : "=r"(lo1), "=r"(hi1) : "l"(acc[i][1]));
            float s = rsqrtf(fmaxf((float)g_degs[grow], 1.0f));
            float ox = (__uint_as_float(lo0) + bias.x) * s;
            float oy = (__uint_as_float(hi0) + bias.y) * s;
            float oz = (__uint_as_float(lo1) + bias.z) * s;
            float ow = (__uint_as_float(hi1) + bias.w) * s;
            __half2 h0 = __floats2half2_rn(ox, oy);
            __half2 h1 = __floats2half2_rn(oz, ow);
            uint2 st;
            st.x = *reinterpret_cast<unsigned*>(&h0);
            st.y = *reinterpret_cast<unsigned*>(&h1);
            *reinterpret_cast<uint2*>(&g_h[grow * LT + c0]) = st;
        }
    }
}

// ---------------------------------------------------------------- agg1 + norm + leaky + GEMM2 + sigmoid
// REWRITTEN: 256 thr = 32 nodes x 8 lanes. Per 8-neighbor batch: one coalesced
// index load per lane, 8 upfront shfls, then 8 INDEPENDENT LDG.128 (MLP=8).
// Lane owns 16B (8 halves) of the 128B row. GEMM2: float4 smem + transposed W1.
__global__ void k_agg1l2(const float* __restrict__ W1,
                         const float* __restrict__ b1, int nn) {
    __shared__ __align__(16) float sW1t[NC * PAD];  // [c][k] transposed
    __shared__ __align__(16) float sact[32][PAD];
    const int tid = threadIdx.x;
    // stage W1 transposed, coalesced global reads (W1 is [k][c], c contiguous)
    for (int i = tid; i < LT * NC; i += 256) {
        int k = i >> 4, c = i & 15;
        sW1t[c * PAD + k] = W1[i];
    }

    const int lane = tid & 31;
    const int grp  = lane >> 3;          // 8-lane group within warp (0..3)
    const int l8   = lane & 7;
    const int slot = (tid >> 5) * 4 + grp;   // node slot 0..31
    const int node = blockIdx.x * 32 + slot;
    const unsigned gmask = 0xFFu << (grp * 8);

    if (node < nn) {
        int beg = g_beg[node];
        int deg = g_degr[node];
        int end = beg + deg;
        float a0 = 0.f, a1 = 0.f, a2 = 0.f, a3 = 0.f;
        float a4 = 0.f, a5 = 0.f, a6 = 0.f, a7 = 0.f;
        const int coff = l8 * 8;          // halves offset: lane's 16B chunk

        for (int b = beg; b < end; b += 8) {
            int t = b + l8;
            int idx = (t < end) ? __ldg(&g_csr[t]) : 0;   // coalesced 32B batch
            int m = end - b;                               // >=1; cap 8 below
            int s[8];
#pragma unroll
            for (int j = 0; j < 8; ++j) s[j] = __shfl_sync(gmask, idx, j, 8);
            uint4 u[8];
#pragma unroll
            for (int j = 0; j < 8; ++j)
                if (j < m) u[j] = *reinterpret_cast<const uint4*>(&g_h[s[j] * LT + coff]);
#pragma unroll
            for (int j = 0; j < 8; ++j) {
                if (j < m) {
                    float2 f0 = __half22float2(*reinterpret_cast<__half2*>(&u[j].x));
                    float2 f1 = __half22float2(*reinterpret_cast<__half2*>(&u[j].y));
                    float2 f2 = __half22float2(*reinterpret_cast<__half2*>(&u[j].z));
                    float2 f3 = __half22float2(*reinterpret_cast<__half2*>(&u[j].w));
                    a0 += f0.x; a1 += f0.y; a2 += f1.x; a3 += f1.y;
                    a4 += f2.x; a5 += f2.y; a6 += f3.x; a7 += f3.y;
                }
            }
        }
        float dr = rsqrtf(fmaxf((float)deg, 1.0f));
        a0 *= dr; a1 *= dr; a2 *= dr; a3 *= dr;
        a4 *= dr; a5 *= dr; a6 *= dr; a7 *= dr;
        a0 = (a0 >= 0.f) ? a0 : NEG * a0;
        a1 = (a1 >= 0.f) ? a1 : NEG * a1;
        a2 = (a2 >= 0.f) ? a2 : NEG * a2;
        a3 = (a3 >= 0.f) ? a3 : NEG * a3;
        a4 = (a4 >= 0.f) ? a4 : NEG * a4;
        a5 = (a5 >= 0.f) ? a5 : NEG * a5;
        a6 = (a6 >= 0.f) ? a6 : NEG * a6;
        a7 = (a7 >= 0.f) ? a7 : NEG * a7;
        float4 st0; st0.x = a0; st0.y = a1; st0.z = a2; st0.w = a3;
        float4 st1; st1.x = a4; st1.y = a5; st1.z = a6; st1.w = a7;
        *reinterpret_cast<float4*>(&sact[slot][coff])     = st0;  // PAD=68 keeps 16B align
        *reinterpret_cast<float4*>(&sact[slot][coff + 4]) = st1;
    }
    __syncthreads();

    // GEMM2: 256 threads cover 16 (node, col) pairs at a time; 2 passes for 32 nodes
    const int c  = tid & 15;
    const int ln = tid >> 4;          // 0..15
    const float* wcol = &sW1t[c * PAD];
#pragma unroll
    for (int h = 0; h < 2; ++h) {
        int sl = h * 16 + ln;
        int node2 = blockIdx.x * 32 + sl;
        if (node2 < nn) {
            float acc = __ldg(&b1[c]);
#pragma unroll
            for (int kg = 0; kg < 16; ++kg) {
                float4 a = *reinterpret_cast<const float4*>(&sact[sl][kg * 4]);
                float4 w = *reinterpret_cast<const float4*>(&wcol[kg * 4]);
                acc += a.x * w.x + a.y * w.y + a.z * w.z + a.w * w.w;
            }
            float zz = 1.0f / (1.0f + __expf(-acc));
            g_z[node2 * NC + c] = __float2half_rn(zz);
        }
    }
}

// ---------------------------------------------------------------- agg2 (R5)
__global__ void k_agg2(float* __restrict__ out, int nn) {
    const int t = blockIdx.x * blockDim.x + threadIdx.x;
    const int node = t >> 1;
    const int c = t & 1;
    if (node >= nn) return;
    int beg = g_beg[node];
    int end = beg + g_degr[node];
    float a[8] = {};
    int i = beg;
    for (; i + 2 <= end; i += 2) {
        int s0 = __ldg(&g_csr[i]);
        int s1 = __ldg(&g_csr[i + 1]);
        uint4 u0 = *reinterpret_cast<const uint4*>(&g_z[s0 * NC + c * 8]);
        uint4 u1 = *reinterpret_cast<const uint4*>(&g_z[s1 * NC + c * 8]);
        float2 f;
        f = __half22float2(*reinterpret_cast<__half2*>(&u0.x)); a[0] += f.x; a[1] += f.y;
        f = __half22float2(*reinterpret_cast<__half2*>(&u0.y)); a[2] += f.x; a[3] += f.y;
        f = __half22float2(*reinterpret_cast<__half2*>(&u0.z)); a[4] += f.x; a[5] += f.y;
        f = __half22float2(*reinterpret_cast<__half2*>(&u0.w)); a[6] += f.x; a[7] += f.y;
        f = __half22float2(*reinterpret_cast<__half2*>(&u1.x)); a[0] += f.x; a[1] += f.y;
        f = __half22float2(*reinterpret_cast<__half2*>(&u1.y)); a[2] += f.x; a[3] += f.y;
        f = __half22float2(*reinterpret_cast<__half2*>(&u1.z)); a[4] += f.x; a[5] += f.y;
        f = __half22float2(*reinterpret_cast<__half2*>(&u1.w)); a[6] += f.x; a[7] += f.y;
    }
    for (; i < end; ++i) {
        int s = __ldg(&g_csr[i]);
        uint4 u = *reinterpret_cast<const uint4*>(&g_z[s * NC + c * 8]);
        float2 f;
        f = __half22float2(*reinterpret_cast<__half2*>(&u.x)); a[0] += f.x; a[1] += f.y;
        f = __half22float2(*reinterpret_cast<__half2*>(&u.y)); a[2] += f.x; a[3] += f.y;
        f = __half22float2(*reinterpret_cast<__half2*>(&u.z)); a[4] += f.x; a[5] += f.y;
        f = __half22float2(*reinterpret_cast<__half2*>(&u.w)); a[6] += f.x; a[7] += f.y;
    }
    float4 o0 = make_float4(a[0], a[1], a[2], a[3]);
    float4 o1 = make_float4(a[4], a[5], a[6], a[7]);
    *reinterpret_cast<float4*>(&out[node * NC + c * 8])     = o0;
    *reinterpret_cast<float4*>(&out[node * NC + c * 8 + 4]) = o1;
}

// ---------------------------------------------------------------- launch (R5 verbatim)
extern "C" void kernel_launch(void* const* d_in, const int* in_sizes, int n_in,
                              void* d_out, int out_size) {
    const float* nodes     = (const float*)d_in[0];
    const int*   senders   = (const int*)  d_in[1];
    const int*   receivers = (const int*)  d_in[2];
    const float* W0        = (const float*)d_in[3];
    const float* b0        = (const float*)d_in[4];
    const float* W1        = (const float*)d_in[5];
    const float* b1        = (const float*)d_in[6];
    float*       out       = (float*)d_out;

    const int nn = in_sizes[0] / DF;
    const int ne = in_sizes[1];
    const int ne4 = (ne + 3) / 4;
    const int eg  = (ne4 + 255) / 256;

    static cudaStream_t s2 = 0;
    static cudaEvent_t evFork = 0, evJoin = 0;
    if (!s2) {
        cudaStreamCreateWithFlags(&s2, cudaStreamNonBlocking);
        cudaEventCreateWithFlags(&evFork, cudaEventDisableTiming);
        cudaEventCreateWithFlags(&evJoin, cudaEventDisableTiming);
    }

    k_init<<<128, 256>>>(nn);
    cudaEventRecord(evFork, 0);

    cudaStreamWaitEvent(s2, evFork, 0);
    k_hist_s<<<eg, 256, 0, s2>>>(senders, ne);
    k_gemm1<<<(nn + 63) / 64, 256, 0, s2>>>(nodes, W0, b0, nn);
    cudaEventRecord(evJoin, s2);

    k_hist_r<<<eg, 256>>>(receivers, ne);
    k_offsets<<<(nn + 255) / 256, 256>>>(nn);
    k_bin<<<eg, 256>>>(senders, receivers, ne);

    cudaStreamWaitEvent(0, evJoin, 0);
    k_agg1l2<<<(nn + 31) / 32, 256>>>(W1, b1, nn);
    k_agg2<<<(nn * 2 + 255) / 256, 256>>>(out, nn);
}